// round 16
// baseline (speedup 1.0000x reference)
#include <cuda_runtime.h>
#include <cuda_bf16.h>
#include <cstdint>

#define B_ 32
#define D_ 128
#define T_ 2250
#define Q_ 32
#define K_ 1024
#define N_ (B_*T_)          // 72000
#define MTILE 64
#define NBLK 1125           // 72000 / 64 exactly
#define WIN 0.02f
#define NC 3                // candidate slots per lane per point

#define EPITCH 264          // bf16 per padded row: [hi 128 | lo 128 | pad 8]
#define ROWB 528            // 528 % 128 == 16 -> LDSM conflict-free

__device__ __align__(16) float g_resid[(size_t)N_ * D_];
__device__ __align__(16) float g_cnorm[Q_ * K_];
__device__ __align__(16) __nv_bfloat16 g_e2[(size_t)Q_ * K_ * EPITCH];

// ---------------------------------------------------------------------------
__global__ void transpose_kernel(const float* __restrict__ in)
{
    __shared__ float tile[32][33];
    const int b  = blockIdx.z;
    const int t0 = blockIdx.x * 32;
    const int d0 = blockIdx.y * 32;
    const int tx = threadIdx.x;
    const int ty = threadIdx.y;

    #pragma unroll
    for (int k = 0; k < 4; k++) {
        int d = d0 + ty + k * 8;
        int t = t0 + tx;
        float v = 0.0f;
        if (t < T_) v = in[((size_t)b * D_ + d) * T_ + t];
        tile[ty + k * 8][tx] = v;
    }
    __syncthreads();
    #pragma unroll
    for (int k = 0; k < 4; k++) {
        int t = t0 + ty + k * 8;
        int d = d0 + tx;
        if (t < T_) g_resid[((size_t)b * T_ + t) * D_ + d] = tile[tx][ty + k * 8];
    }
}

// ---------------------------------------------------------------------------
__global__ void cnorm_kernel(const float* __restrict__ embed)
{
    const int wid  = threadIdx.x >> 5;
    const int lane = threadIdx.x & 31;
    const int code = blockIdx.x * 8 + wid;
    float s = 0.0f;
    #pragma unroll
    for (int j = 0; j < 4; j++) {
        float v = embed[(size_t)code * D_ + lane + 32 * j];
        s = fmaf(v, v, s);
    }
    #pragma unroll
    for (int d = 16; d; d >>= 1) s += __shfl_xor_sync(0xffffffffu, s, d);
    if (lane == 0) g_cnorm[code] = s;
}

// ---------------------------------------------------------------------------
// [e_hi(128) | e_lo(128) | pad(8)=0], pitch EPITCH=264 bf16 (528 B)
__global__ void prep_e2_kernel(const float* __restrict__ embed)
{
    const int row = blockIdx.x;
    const int d   = threadIdx.x;
    float v = embed[(size_t)row * D_ + d];
    __nv_bfloat16 hi = __float2bfloat16(v);
    __nv_bfloat16 lo = __float2bfloat16(v - __bfloat162float(hi));
    g_e2[(size_t)row * EPITCH + d]       = hi;
    g_e2[(size_t)row * EPITCH + 128 + d] = lo;
    if (d < 8) g_e2[(size_t)row * EPITCH + 256 + d] = __float2bfloat16(0.0f);
}

// ---------------------------------------------------------------------------
__device__ __forceinline__ uint32_t smem_u32(const void* p) {
    uint32_t a;
    asm("{ .reg .u64 t; cvta.to.shared.u64 t, %1; cvt.u32.u64 %0, t; }"
        : "=r"(a) : "l"(p));
    return a;
}
__device__ __forceinline__ void ldsm_x4(uint32_t& r0, uint32_t& r1,
                                        uint32_t& r2, uint32_t& r3, uint32_t addr)
{
    asm volatile("ldmatrix.sync.aligned.m8n8.x4.shared.b16 {%0,%1,%2,%3}, [%4];"
                 : "=r"(r0), "=r"(r1), "=r"(r2), "=r"(r3) : "r"(addr));
}
__device__ __forceinline__ void mma16816(float* c, const uint32_t* a,
                                         uint32_t b0, uint32_t b1)
{
    asm volatile(
        "mma.sync.aligned.m16n8k16.row.col.f32.bf16.bf16.f32 "
        "{%0,%1,%2,%3}, {%4,%5,%6,%7}, {%8,%9}, {%0,%1,%2,%3};"
        : "+f"(c[0]), "+f"(c[1]), "+f"(c[2]), "+f"(c[3])
        : "r"(a[0]), "r"(a[1]), "r"(a[2]), "r"(a[3]), "r"(b0), "r"(b1));
}
__device__ __forceinline__ void cp_async16(void* smem_dst, const void* gmem_src)
{
    unsigned saddr = (unsigned)__cvta_generic_to_shared(smem_dst);
    asm volatile("cp.async.cg.shared.global [%0], [%1], 16;"
                 :: "r"(saddr), "l"(gmem_src) : "memory");
}
__device__ __forceinline__ void cp_async_commit()
{ asm volatile("cp.async.commit_group;" ::: "memory"); }
__device__ __forceinline__ void cp_async_wait_all()
{ asm volatile("cp.async.wait_group 0;" ::: "memory"); }

#define CAND_UPD(s, idx, mb, cs, ci, cn, ovf) do {                            \
    if ((s) > (mb)) (mb) = (s);                                               \
    if ((s) >= (mb) - WIN) {                                                  \
        if ((cn) < NC) { (cs)[(cn)] = (s); (ci)[(cn)] = (idx); (cn)++; }      \
        else {                                                                \
            int _w = 0;                                                       \
            _Pragma("unroll")                                                 \
            for (int _t = 0; _t < NC; _t++)                                   \
                if ((cs)[_t] >= (mb) - WIN) {                                 \
                    (cs)[_w] = (cs)[_t]; (ci)[_w] = (ci)[_t]; _w++; }         \
            if (_w < NC) { (cs)[_w] = (s); (ci)[_w] = (idx); (cn) = _w + 1; } \
            else (ovf) = 1;                                                   \
        }                                                                     \
    }                                                                         \
} while (0)

// ---------------------------------------------------------------------------
// HMMA RVQ layer: 128 threads (4 warps), 64 points/block, 3 CTAs/SM.
// A' fragments deduped: a_hi[8][4] (k 0..7) + a_lo[8][4]; MMA passes
// hi*b_hi, hi*b_lo, lo*b_hi reproduce [r_hi|r_hi|r_lo].[e_hi|e_lo|e_hi]
// in the SAME order -> bit-identical to R12/R15 scores. B in 2-section
// [e_hi|e_lo] rows (528 B pitch), cp.async double-buffered. Two-phase scan,
// windowed candidates, exact fp32 rescore (R7 f32x2 order) unchanged.
// smem/block: B0 (= A staging) 33792 + B1 33792 + cn 4096 + sidx 256.
// ---------------------------------------------------------------------------
#define SM_B0   0
#define SM_B1   33792
#define SM_CN   67584
#define SM_SIDX 71680
#define SM_TOTAL 71936

__global__ void __launch_bounds__(128, 3)
rvq_mma_kernel(const float* __restrict__ embed, int q, float* __restrict__ out)
{
    extern __shared__ char smem[];
    float* gcn  = (float*)(smem + SM_CN);
    int*   sidx = (int*)(smem + SM_SIDX);
    const uint32_t sbase = smem_u32(smem);

    const int tid  = threadIdx.x;
    const int wid  = tid >> 5;          // 0..3, owns M-rows [wid*16, wid*16+16)
    const int lane = tid & 31;
    const int blockStart = blockIdx.x * MTILE;

    // ---- cnorm -> smem ----
    for (int u = tid; u < K_; u += 128) gcn[u] = g_cnorm[q * K_ + u];

    // ---- build A' staging = [r_hi | r_lo] (64 x 256 bf16, pitch 528B) ----
    for (int u = tid; u < MTILE * 32; u += 128) {
        int row = u >> 5, g = u & 31;
        int sec = g >> 4;               // 0 = hi, 1 = lo
        int dbase = (g & 15) * 8;
        const float* rr = g_resid + (size_t)(blockStart + row) * D_;
        union { __nv_bfloat16 h[8]; uint4 v; } pk;
        #pragma unroll
        for (int j = 0; j < 8; j++) {
            float v = rr[dbase + j];
            __nv_bfloat16 hi = __float2bfloat16(v);
            pk.h[j] = (sec == 0) ? hi : __float2bfloat16(v - __bfloat162float(hi));
        }
        *(uint4*)(smem + row * ROWB + g * 16) = pk.v;
    }
    if (tid < MTILE)   // zero pad column (bytes 512..527)
        *(uint4*)(smem + tid * ROWB + 512) = make_uint4(0, 0, 0, 0);
    __syncthreads();

    // ---- A fragments -> registers: a_hi (k16 0..7), a_lo (0..7) ----
    const int rsel = lane & 15;
    const int ksel = (lane >> 4) << 4;
    uint32_t a_hi[8][4], a_lo[8][4];
    {
        const uint32_t ab = sbase + (wid * 16 + rsel) * ROWB + ksel;
        #pragma unroll
        for (int ks = 0; ks < 8; ks++)
            ldsm_x4(a_hi[ks][0], a_hi[ks][1], a_hi[ks][2], a_hi[ks][3],
                    ab + ks * 32);
        #pragma unroll
        for (int ks = 0; ks < 8; ks++)
            ldsm_x4(a_lo[ks][0], a_lo[ks][1], a_lo[ks][2], a_lo[ks][3],
                    ab + 256 + ks * 32);
    }
    __syncthreads();   // staging dead -> becomes B buffer 0

    // ---- prefetch B chunk 0 (64 rows x 33 uint4) ----
    {
        const uint4* src = (const uint4*)(g_e2 + (size_t)(q * K_) * EPITCH);
        #pragma unroll
        for (int r = 0; r < 16; r++) {
            int row = wid * 16 + r;
            const uint4* s = src + (size_t)row * 33;
            char* d = smem + SM_B0 + row * ROWB;
            cp_async16(d + lane * 16, s + lane);
            if (lane == 0) cp_async16(d + 512, s + 32);
        }
        cp_async_commit();
    }

    float mb0 = -3.4e38f, mb1 = -3.4e38f;
    float cs0[NC], cs1[NC];
    int   ci0[NC], ci1[NC];
    int   cn0 = 0, cn1 = 0, ovf0 = 0, ovf1 = 0;

    const uint32_t bsel = rsel * ROWB + ksel;

    for (int ch = 0; ch < 16; ++ch) {
        cp_async_wait_all();
        __syncthreads();   // buffer ch&1 ready; prior readers done with it

        if (ch < 15) {
            const uint4* src = (const uint4*)(g_e2 +
                (size_t)(q * K_ + (ch + 1) * 64) * EPITCH);
            char* dst = smem + (((ch + 1) & 1) ? SM_B1 : SM_B0);
            #pragma unroll
            for (int r = 0; r < 16; r++) {
                int row = wid * 16 + r;
                const uint4* s = src + (size_t)row * 33;
                char* d = dst + row * ROWB;
                cp_async16(d + lane * 16, s + lane);
                if (lane == 0) cp_async16(d + 512, s + 32);
            }
        }
        cp_async_commit();

        const uint32_t bb = sbase + ((ch & 1) ? SM_B1 : SM_B0) + bsel;

        float acc[8][4];
        #pragma unroll
        for (int i = 0; i < 8; i++)
            acc[i][0] = acc[i][1] = acc[i][2] = acc[i][3] = 0.0f;

        // pass 1: r_hi . e_hi
        #pragma unroll
        for (int ks = 0; ks < 8; ++ks) {
            #pragma unroll
            for (int n16 = 0; n16 < 4; n16++) {
                uint32_t b0, b1, b2, b3;
                ldsm_x4(b0, b1, b2, b3, bb + n16 * (16 * ROWB) + ks * 32);
                mma16816(acc[2 * n16],     a_hi[ks], b0, b2);
                mma16816(acc[2 * n16 + 1], a_hi[ks], b1, b3);
            }
        }
        // pass 2: r_hi . e_lo
        #pragma unroll
        for (int ks = 0; ks < 8; ++ks) {
            #pragma unroll
            for (int n16 = 0; n16 < 4; n16++) {
                uint32_t b0, b1, b2, b3;
                ldsm_x4(b0, b1, b2, b3, bb + n16 * (16 * ROWB) + 256 + ks * 32);
                mma16816(acc[2 * n16],     a_hi[ks], b0, b2);
                mma16816(acc[2 * n16 + 1], a_hi[ks], b1, b3);
            }
        }
        // pass 3: r_lo . e_hi
        #pragma unroll
        for (int ks = 0; ks < 8; ++ks) {
            #pragma unroll
            for (int n16 = 0; n16 < 4; n16++) {
                uint32_t b0, b1, b2, b3;
                ldsm_x4(b0, b1, b2, b3, bb + n16 * (16 * ROWB) + ks * 32);
                mma16816(acc[2 * n16],     a_lo[ks], b0, b2);
                mma16816(acc[2 * n16 + 1], a_lo[ks], b1, b3);
            }
        }

        // ---- two-phase scan ----
        float cnv[16];
        #pragma unroll
        for (int n8 = 0; n8 < 8; n8++) {
            const int ncol = n8 * 8 + (lane & 3) * 2;
            cnv[2 * n8]     = gcn[ch * 64 + ncol];
            cnv[2 * n8 + 1] = gcn[ch * 64 + ncol + 1];
        }
        float smax0 = -3.4e38f, smax1 = -3.4e38f;
        #pragma unroll
        for (int n8 = 0; n8 < 8; n8++) {
            #pragma unroll
            for (int e = 0; e < 2; e++) {
                smax0 = fmaxf(smax0, fmaf(2.0f, acc[n8][e],     -cnv[2 * n8 + e]));
                smax1 = fmaxf(smax1, fmaf(2.0f, acc[n8][2 + e], -cnv[2 * n8 + e]));
            }
        }
        if (smax0 >= mb0 - WIN) {
            #pragma unroll
            for (int n8 = 0; n8 < 8; n8++) {
                const int ncol = n8 * 8 + (lane & 3) * 2;
                #pragma unroll
                for (int e = 0; e < 2; e++) {
                    const int idx = ch * 64 + ncol + e;
                    const float s = fmaf(2.0f, acc[n8][e], -cnv[2 * n8 + e]);
                    CAND_UPD(s, idx, mb0, cs0, ci0, cn0, ovf0);
                }
            }
        }
        if (smax1 >= mb1 - WIN) {
            #pragma unroll
            for (int n8 = 0; n8 < 8; n8++) {
                const int ncol = n8 * 8 + (lane & 3) * 2;
                #pragma unroll
                for (int e = 0; e < 2; e++) {
                    const int idx = ch * 64 + ncol + e;
                    const float s = fmaf(2.0f, acc[n8][2 + e], -cnv[2 * n8 + e]);
                    CAND_UPD(s, idx, mb1, cs1, ci1, cn1, ovf1);
                }
            }
        }
    }
    cp_async_wait_all();

    // ---- per-point merge + exact rescore ----
    const int prow0 = wid * 16 + (lane >> 2);
    const int prow1 = prow0 + 8;
    float gm0 = mb0, gm1 = mb1;
    #pragma unroll
    for (int d = 1; d < 4; d <<= 1) {
        gm0 = fmaxf(gm0, __shfl_xor_sync(0xffffffffu, gm0, d));
        gm1 = fmaxf(gm1, __shfl_xor_sync(0xffffffffu, gm1, d));
        ovf0 |= __shfl_xor_sync(0xffffffffu, ovf0, d);
        ovf1 |= __shfl_xor_sync(0xffffffffu, ovf1, d);
    }

    const int n0 = blockStart + prow0;
    const int n1 = blockStart + prow1;

    auto score_exact = [&](int nn, int idx) -> float {
        const float* rr = g_resid + (size_t)nn * D_;
        const float* e  = embed + ((size_t)q * K_ + idx) * D_;
        float aLo = 0.0f, aHi = 0.0f;
        #pragma unroll 4
        for (int d4 = 0; d4 < 32; d4++) {
            aLo = fmaf(rr[d4 * 4 + 0], __ldg(&e[d4 * 4 + 0]), aLo);
            aHi = fmaf(rr[d4 * 4 + 1], __ldg(&e[d4 * 4 + 1]), aHi);
            aLo = fmaf(rr[d4 * 4 + 2], __ldg(&e[d4 * 4 + 2]), aLo);
            aHi = fmaf(rr[d4 * 4 + 3], __ldg(&e[d4 * 4 + 3]), aHi);
        }
        return 2.0f * (aLo + aHi) - gcn[idx];
    };

    float bE0 = -3.4e38f, bE1 = -3.4e38f;
    int   bI0 = 0x7fffffff, bI1 = 0x7fffffff;
    for (int t = 0; t < cn0; t++) {
        if (cs0[t] < gm0 - WIN) continue;
        const float s = score_exact(n0, ci0[t]);
        if (s > bE0 || (s == bE0 && ci0[t] < bI0)) { bE0 = s; bI0 = ci0[t]; }
    }
    for (int t = 0; t < cn1; t++) {
        if (cs1[t] < gm1 - WIN) continue;
        const float s = score_exact(n1, ci1[t]);
        if (s > bE1 || (s == bE1 && ci1[t] < bI1)) { bE1 = s; bI1 = ci1[t]; }
    }
    #pragma unroll
    for (int d = 1; d < 4; d <<= 1) {
        const float oe0 = __shfl_xor_sync(0xffffffffu, bE0, d);
        const int   oi0 = __shfl_xor_sync(0xffffffffu, bI0, d);
        if (oe0 > bE0 || (oe0 == bE0 && oi0 < bI0)) { bE0 = oe0; bI0 = oi0; }
        const float oe1 = __shfl_xor_sync(0xffffffffu, bE1, d);
        const int   oi1 = __shfl_xor_sync(0xffffffffu, bI1, d);
        if (oe1 > bE1 || (oe1 == bE1 && oi1 < bI1)) { bE1 = oe1; bI1 = oi1; }
    }
    if ((lane & 3) == 0) {
        if (ovf0) {
            bE0 = -3.4e38f; bI0 = 0;
            for (int idx = 0; idx < K_; idx++) {
                const float s = score_exact(n0, idx);
                if (s > bE0) { bE0 = s; bI0 = idx; }
            }
        }
        if (ovf1) {
            bE1 = -3.4e38f; bI1 = 0;
            for (int idx = 0; idx < K_; idx++) {
                const float s = score_exact(n1, idx);
                if (s > bE1) { bE1 = s; bI1 = idx; }
            }
        }
        sidx[prow0] = (bI0 == 0x7fffffff) ? 0 : bI0;
        sidx[prow1] = (bI1 == 0x7fffffff) ? 0 : bI1;
    }
    __syncthreads();

    // ---- write indices as float ----
    if (tid < MTILE) out[(size_t)q * N_ + blockStart + tid] = (float)sidx[tid];

    // ---- residual update: r - e[best] -> g_resid ----
    const float4* eq4 = (const float4*)(embed + (size_t)q * K_ * D_);
    float4* rg4 = (float4*)g_resid;
    #pragma unroll
    for (int i = 0; i < 16; i++) {
        int f = tid + 128 * i;
        int pp = f >> 5, d4 = f & 31;
        int n = blockStart + pp;
        float4 r = rg4[(size_t)n * 32 + d4];
        float4 e = eq4[(size_t)sidx[pp] * 32 + d4];
        float4 w;
        w.x = r.x - e.x; w.y = r.y - e.y; w.z = r.z - e.z; w.w = r.w - e.w;
        rg4[(size_t)n * 32 + d4] = w;
    }
}

// ---------------------------------------------------------------------------
extern "C" void kernel_launch(void* const* d_in, const int* in_sizes, int n_in,
                              void* d_out, int out_size)
{
    const float* embeddings = (const float*)d_in[0];
    const float* embed      = (const float*)d_in[1];
    if (n_in >= 2 && in_sizes[0] == Q_ * K_ * D_ && in_sizes[1] == B_ * D_ * T_) {
        const float* t = embeddings; embeddings = embed; embed = t;
    }
    float* out = (float*)d_out;

    cudaFuncSetAttribute(rvq_mma_kernel,
                         cudaFuncAttributeMaxDynamicSharedMemorySize, SM_TOTAL);

    transpose_kernel<<<dim3(71, 4, 32), dim3(32, 8)>>>(embeddings);
    cnorm_kernel<<<4096, 256>>>(embed);
    prep_e2_kernel<<<Q_ * K_, 128>>>(embed);
    for (int q = 0; q < Q_; q++) {
        rvq_mma_kernel<<<NBLK, 128, SM_TOTAL>>>(embed, q, out);
    }
}

// round 17
// speedup vs baseline: 1.0432x; 1.0432x over previous
#include <cuda_runtime.h>
#include <cuda_bf16.h>
#include <cstdint>

#define B_ 32
#define D_ 128
#define T_ 2250
#define Q_ 32
#define K_ 1024
#define N_ (B_*T_)          // 72000
#define PTILE 256           // 128 HMMA points + 128 SIMT points per block
#define NBLK 282            // ceil(72000/256)
#define WIN 0.02f
#define NC 3

#define EPITCH 264          // [e_hi 128 | e_lo 128 | pad 8] bf16 (528 B)
#define ROWB 528

__device__ __align__(16) float g_resid[(size_t)N_ * D_];
__device__ __align__(16) float g_cnorm[Q_ * K_];
__device__ __align__(16) __nv_bfloat16 g_e2[(size_t)Q_ * K_ * EPITCH];

// ---------------------------------------------------------------------------
__global__ void transpose_kernel(const float* __restrict__ in)
{
    __shared__ float tile[32][33];
    const int b  = blockIdx.z;
    const int t0 = blockIdx.x * 32;
    const int d0 = blockIdx.y * 32;
    const int tx = threadIdx.x;
    const int ty = threadIdx.y;

    #pragma unroll
    for (int k = 0; k < 4; k++) {
        int d = d0 + ty + k * 8;
        int t = t0 + tx;
        float v = 0.0f;
        if (t < T_) v = in[((size_t)b * D_ + d) * T_ + t];
        tile[ty + k * 8][tx] = v;
    }
    __syncthreads();
    #pragma unroll
    for (int k = 0; k < 4; k++) {
        int t = t0 + ty + k * 8;
        int d = d0 + tx;
        if (t < T_) g_resid[((size_t)b * T_ + t) * D_ + d] = tile[tx][ty + k * 8];
    }
}

// ---------------------------------------------------------------------------
__global__ void cnorm_kernel(const float* __restrict__ embed)
{
    const int wid  = threadIdx.x >> 5;
    const int lane = threadIdx.x & 31;
    const int code = blockIdx.x * 8 + wid;
    float s = 0.0f;
    #pragma unroll
    for (int j = 0; j < 4; j++) {
        float v = embed[(size_t)code * D_ + lane + 32 * j];
        s = fmaf(v, v, s);
    }
    #pragma unroll
    for (int d = 16; d; d >>= 1) s += __shfl_xor_sync(0xffffffffu, s, d);
    if (lane == 0) g_cnorm[code] = s;
}

// ---------------------------------------------------------------------------
__global__ void prep_e2_kernel(const float* __restrict__ embed)
{
    const int row = blockIdx.x;
    const int d   = threadIdx.x;
    float v = embed[(size_t)row * D_ + d];
    __nv_bfloat16 hi = __float2bfloat16(v);
    __nv_bfloat16 lo = __float2bfloat16(v - __bfloat162float(hi));
    g_e2[(size_t)row * EPITCH + d]       = hi;
    g_e2[(size_t)row * EPITCH + 128 + d] = lo;
    if (d < 8) g_e2[(size_t)row * EPITCH + 256 + d] = __float2bfloat16(0.0f);
}

// ---------------------------------------------------------------------------
__device__ __forceinline__ uint32_t smem_u32(const void* p) {
    uint32_t a;
    asm("{ .reg .u64 t; cvta.to.shared.u64 t, %1; cvt.u32.u64 %0, t; }"
        : "=r"(a) : "l"(p));
    return a;
}
__device__ __forceinline__ void ldsm_x4(uint32_t& r0, uint32_t& r1,
                                        uint32_t& r2, uint32_t& r3, uint32_t addr)
{
    asm volatile("ldmatrix.sync.aligned.m8n8.x4.shared.b16 {%0,%1,%2,%3}, [%4];"
                 : "=r"(r0), "=r"(r1), "=r"(r2), "=r"(r3) : "r"(addr));
}
__device__ __forceinline__ void mma16816(float* c, const uint32_t* a,
                                         uint32_t b0, uint32_t b1)
{
    asm volatile(
        "mma.sync.aligned.m16n8k16.row.col.f32.bf16.bf16.f32 "
        "{%0,%1,%2,%3}, {%4,%5,%6,%7}, {%8,%9}, {%0,%1,%2,%3};"
        : "+f"(c[0]), "+f"(c[1]), "+f"(c[2]), "+f"(c[3])
        : "r"(a[0]), "r"(a[1]), "r"(a[2]), "r"(a[3]), "r"(b0), "r"(b1));
}
__device__ __forceinline__ void ffma2(unsigned long long& acc,
                                      unsigned long long a,
                                      unsigned long long b)
{
    asm("fma.rn.f32x2 %0, %1, %2, %0;" : "+l"(acc) : "l"(a), "l"(b));
}
__device__ __forceinline__ void cp_async16(void* smem_dst, const void* gmem_src)
{
    unsigned saddr = (unsigned)__cvta_generic_to_shared(smem_dst);
    asm volatile("cp.async.cg.shared.global [%0], [%1], 16;"
                 :: "r"(saddr), "l"(gmem_src) : "memory");
}
__device__ __forceinline__ void cp_async_commit()
{ asm volatile("cp.async.commit_group;" ::: "memory"); }
__device__ __forceinline__ void cp_async_wait_all()
{ asm volatile("cp.async.wait_group 0;" ::: "memory"); }

#define BAR_H() asm volatile("bar.sync 1, 256;" ::: "memory")
#define BAR_S() asm volatile("bar.sync 2, 256;" ::: "memory")

#define CAND_UPD(s, idx, mb, cs, ci, cn, ovf) do {                            \
    if ((s) > (mb)) (mb) = (s);                                               \
    if ((s) >= (mb) - WIN) {                                                  \
        if ((cn) < NC) { (cs)[(cn)] = (s); (ci)[(cn)] = (idx); (cn)++; }      \
        else {                                                                \
            int _w = 0;                                                       \
            _Pragma("unroll")                                                 \
            for (int _t = 0; _t < NC; _t++)                                   \
                if ((cs)[_t] >= (mb) - WIN) {                                 \
                    (cs)[_w] = (cs)[_t]; (ci)[_w] = (ci)[_t]; _w++; }         \
            if (_w < NC) { (cs)[_w] = (s); (ci)[_w] = (idx); (cn) = _w + 1; } \
            else (ovf) = 1;                                                   \
        }                                                                     \
    }                                                                         \
} while (0)

// ---------------------------------------------------------------------------
// Hybrid RVQ layer: 512 threads. Warps 0-7 = HMMA engine on points
// [blockStart, +128); warps 8-15 = SIMT f32x2 engine on [blockStart+128,
// +256). Named barriers keep the halves independent; both engines are the
// exact validated R15/R16 (HMMA+rescore) and R5 (f32x2) pipelines, which
// produce identical indices (rel_err 0.000890055).
// smem: HMMA A/B region 67584 | SIMT r 67584 | SIMT e 33792 | cn 4096 |
//       sidx 1024  = 174080 B.
// ---------------------------------------------------------------------------
#define SM_B0   0
#define SM_B1   33792
#define SM_SR   67584
#define SM_SE   135168
#define SM_CN   168960
#define SM_SIDX 173056
#define SM_TOTAL 174080

__global__ void __launch_bounds__(512, 1)
rvq_hybrid_kernel(const float* __restrict__ embed, int q, float* __restrict__ out)
{
    extern __shared__ char smem[];
    float* gcn  = (float*)(smem + SM_CN);
    int*   sidx = (int*)(smem + SM_SIDX);
    const uint32_t sbase = smem_u32(smem);

    const int tid = threadIdx.x;
    const int blockStart = blockIdx.x * PTILE;

    for (int u = tid; u < K_; u += 512) gcn[u] = g_cnorm[q * K_ + u];
    __syncthreads();

    if (tid < 256) {
        // ================= HMMA half: points blockStart .. +127 ===========
        const int wid  = tid >> 5;       // 0..7
        const int lane = tid & 31;

        // A' staging [r_hi | r_lo], 128 rows x 528 B
        for (int u = tid; u < 128 * 32; u += 256) {
            int row = u >> 5, g = u & 31;
            int sec = g >> 4;
            int dbase = (g & 15) * 8;
            int n = blockStart + row;
            if (n >= N_) n = 0;
            const float* rr = g_resid + (size_t)n * D_;
            union { __nv_bfloat16 h[8]; uint4 v; } pk;
            #pragma unroll
            for (int j = 0; j < 8; j++) {
                float v = rr[dbase + j];
                __nv_bfloat16 hi = __float2bfloat16(v);
                pk.h[j] = (sec == 0) ? hi
                                     : __float2bfloat16(v - __bfloat162float(hi));
            }
            *(uint4*)(smem + row * ROWB + g * 16) = pk.v;
        }
        for (int row = tid; row < 128; row += 256)
            *(uint4*)(smem + row * ROWB + 512) = make_uint4(0, 0, 0, 0);
        BAR_H();

        const int rsel = lane & 15;
        const int ksel = (lane >> 4) << 4;
        uint32_t a_hi[8][4], a_lo[8][4];
        {
            const uint32_t ab = sbase + (wid * 16 + rsel) * ROWB + ksel;
            #pragma unroll
            for (int ks = 0; ks < 8; ks++)
                ldsm_x4(a_hi[ks][0], a_hi[ks][1], a_hi[ks][2], a_hi[ks][3],
                        ab + ks * 32);
            #pragma unroll
            for (int ks = 0; ks < 8; ks++)
                ldsm_x4(a_lo[ks][0], a_lo[ks][1], a_lo[ks][2], a_lo[ks][3],
                        ab + 256 + ks * 32);
        }
        BAR_H();   // staging dead -> B double buffer

        {   // prefetch B chunk 0
            const uint4* src = (const uint4*)(g_e2 + (size_t)(q * K_) * EPITCH);
            #pragma unroll
            for (int r = 0; r < 8; r++) {
                int row = wid * 8 + r;
                const uint4* s = src + (size_t)row * 33;
                char* d = smem + SM_B0 + row * ROWB;
                cp_async16(d + lane * 16, s + lane);
                if (lane == 0) cp_async16(d + 512, s + 32);
            }
            cp_async_commit();
        }

        float mb0 = -3.4e38f, mb1 = -3.4e38f;
        float cs0[NC], cs1[NC];
        int   ci0[NC], ci1[NC];
        int   cn0 = 0, cn1 = 0, ovf0 = 0, ovf1 = 0;
        const uint32_t bsel = rsel * ROWB + ksel;
        const int lq = (lane & 3) * 2;

        for (int ch = 0; ch < 16; ++ch) {
            cp_async_wait_all();
            BAR_H();

            if (ch < 15) {
                const uint4* src = (const uint4*)(g_e2 +
                    (size_t)(q * K_ + (ch + 1) * 64) * EPITCH);
                char* dst = smem + (((ch + 1) & 1) ? SM_B1 : SM_B0);
                #pragma unroll
                for (int r = 0; r < 8; r++) {
                    int row = wid * 8 + r;
                    const uint4* s = src + (size_t)row * 33;
                    char* d = dst + row * ROWB;
                    cp_async16(d + lane * 16, s + lane);
                    if (lane == 0) cp_async16(d + 512, s + 32);
                }
            }
            cp_async_commit();

            const uint32_t bb = sbase + ((ch & 1) ? SM_B1 : SM_B0) + bsel;

            float acc[8][4];
            #pragma unroll
            for (int i = 0; i < 8; i++)
                acc[i][0] = acc[i][1] = acc[i][2] = acc[i][3] = 0.0f;

            // pass 1: r_hi . e_hi
            #pragma unroll
            for (int ks = 0; ks < 8; ++ks)
                #pragma unroll
                for (int n16 = 0; n16 < 4; n16++) {
                    uint32_t b0, b1, b2, b3;
                    ldsm_x4(b0, b1, b2, b3, bb + n16 * (16 * ROWB) + ks * 32);
                    mma16816(acc[2 * n16],     a_hi[ks], b0, b2);
                    mma16816(acc[2 * n16 + 1], a_hi[ks], b1, b3);
                }
            // pass 2: r_hi . e_lo
            #pragma unroll
            for (int ks = 0; ks < 8; ++ks)
                #pragma unroll
                for (int n16 = 0; n16 < 4; n16++) {
                    uint32_t b0, b1, b2, b3;
                    ldsm_x4(b0, b1, b2, b3, bb + n16 * (16 * ROWB) + 256 + ks * 32);
                    mma16816(acc[2 * n16],     a_hi[ks], b0, b2);
                    mma16816(acc[2 * n16 + 1], a_hi[ks], b1, b3);
                }
            // pass 3: r_lo . e_hi
            #pragma unroll
            for (int ks = 0; ks < 8; ++ks)
                #pragma unroll
                for (int n16 = 0; n16 < 4; n16++) {
                    uint32_t b0, b1, b2, b3;
                    ldsm_x4(b0, b1, b2, b3, bb + n16 * (16 * ROWB) + ks * 32);
                    mma16816(acc[2 * n16],     a_lo[ks], b0, b2);
                    mma16816(acc[2 * n16 + 1], a_lo[ks], b1, b3);
                }

            // two-phase scan (gcn read inline)
            float smax0 = -3.4e38f, smax1 = -3.4e38f;
            #pragma unroll
            for (int n8 = 0; n8 < 8; n8++) {
                #pragma unroll
                for (int e = 0; e < 2; e++) {
                    const float cnv = gcn[ch * 64 + n8 * 8 + lq + e];
                    smax0 = fmaxf(smax0, fmaf(2.0f, acc[n8][e],     -cnv));
                    smax1 = fmaxf(smax1, fmaf(2.0f, acc[n8][2 + e], -cnv));
                }
            }
            if (smax0 >= mb0 - WIN) {
                #pragma unroll
                for (int n8 = 0; n8 < 8; n8++)
                    #pragma unroll
                    for (int e = 0; e < 2; e++) {
                        const int idx = ch * 64 + n8 * 8 + lq + e;
                        const float s = fmaf(2.0f, acc[n8][e], -gcn[idx]);
                        CAND_UPD(s, idx, mb0, cs0, ci0, cn0, ovf0);
                    }
            }
            if (smax1 >= mb1 - WIN) {
                #pragma unroll
                for (int n8 = 0; n8 < 8; n8++)
                    #pragma unroll
                    for (int e = 0; e < 2; e++) {
                        const int idx = ch * 64 + n8 * 8 + lq + e;
                        const float s = fmaf(2.0f, acc[n8][2 + e], -gcn[idx]);
                        CAND_UPD(s, idx, mb1, cs1, ci1, cn1, ovf1);
                    }
            }
        }
        cp_async_wait_all();

        // merge + exact rescore
        const int prow0 = wid * 16 + (lane >> 2);
        const int prow1 = prow0 + 8;
        float gm0 = mb0, gm1 = mb1;
        #pragma unroll
        for (int d = 1; d < 4; d <<= 1) {
            gm0 = fmaxf(gm0, __shfl_xor_sync(0xffffffffu, gm0, d));
            gm1 = fmaxf(gm1, __shfl_xor_sync(0xffffffffu, gm1, d));
            ovf0 |= __shfl_xor_sync(0xffffffffu, ovf0, d);
            ovf1 |= __shfl_xor_sync(0xffffffffu, ovf1, d);
        }
        int n0 = blockStart + prow0; if (n0 >= N_) n0 = 0;
        int n1 = blockStart + prow1; if (n1 >= N_) n1 = 0;

        auto score_exact = [&](int nn, int idx) -> float {
            const float* rr = g_resid + (size_t)nn * D_;
            const float* e  = embed + ((size_t)q * K_ + idx) * D_;
            float aLo = 0.0f, aHi = 0.0f;
            #pragma unroll 4
            for (int d4 = 0; d4 < 32; d4++) {
                aLo = fmaf(rr[d4 * 4 + 0], __ldg(&e[d4 * 4 + 0]), aLo);
                aHi = fmaf(rr[d4 * 4 + 1], __ldg(&e[d4 * 4 + 1]), aHi);
                aLo = fmaf(rr[d4 * 4 + 2], __ldg(&e[d4 * 4 + 2]), aLo);
                aHi = fmaf(rr[d4 * 4 + 3], __ldg(&e[d4 * 4 + 3]), aHi);
            }
            return 2.0f * (aLo + aHi) - gcn[idx];
        };

        float bE0 = -3.4e38f, bE1 = -3.4e38f;
        int   bI0 = 0x7fffffff, bI1 = 0x7fffffff;
        for (int t = 0; t < cn0; t++) {
            if (cs0[t] < gm0 - WIN) continue;
            const float s = score_exact(n0, ci0[t]);
            if (s > bE0 || (s == bE0 && ci0[t] < bI0)) { bE0 = s; bI0 = ci0[t]; }
        }
        for (int t = 0; t < cn1; t++) {
            if (cs1[t] < gm1 - WIN) continue;
            const float s = score_exact(n1, ci1[t]);
            if (s > bE1 || (s == bE1 && ci1[t] < bI1)) { bE1 = s; bI1 = ci1[t]; }
        }
        #pragma unroll
        for (int d = 1; d < 4; d <<= 1) {
            const float oe0 = __shfl_xor_sync(0xffffffffu, bE0, d);
            const int   oi0 = __shfl_xor_sync(0xffffffffu, bI0, d);
            if (oe0 > bE0 || (oe0 == bE0 && oi0 < bI0)) { bE0 = oe0; bI0 = oi0; }
            const float oe1 = __shfl_xor_sync(0xffffffffu, bE1, d);
            const int   oi1 = __shfl_xor_sync(0xffffffffu, bI1, d);
            if (oe1 > bE1 || (oe1 == bE1 && oi1 < bI1)) { bE1 = oe1; bI1 = oi1; }
        }
        if ((lane & 3) == 0) {
            if (ovf0) {
                bE0 = -3.4e38f; bI0 = 0;
                for (int idx = 0; idx < K_; idx++) {
                    const float s = score_exact(n0, idx);
                    if (s > bE0) { bE0 = s; bI0 = idx; }
                }
            }
            if (ovf1) {
                bE1 = -3.4e38f; bI1 = 0;
                for (int idx = 0; idx < K_; idx++) {
                    const float s = score_exact(n1, idx);
                    if (s > bE1) { bE1 = s; bI1 = idx; }
                }
            }
            sidx[prow0] = (bI0 == 0x7fffffff) ? 0 : bI0;
            sidx[prow1] = (bI1 == 0x7fffffff) ? 0 : bI1;
        }
        BAR_H();

        if (tid < 128) {
            int n = blockStart + tid;
            if (n < N_) out[(size_t)q * N_ + n] = (float)sidx[tid];
        }
        const float4* eq4 = (const float4*)(embed + (size_t)q * K_ * D_);
        float4* rg4 = (float4*)g_resid;
        #pragma unroll
        for (int i = 0; i < 16; i++) {
            int f = tid + 256 * i;
            int pp = f >> 5, d4 = f & 31;
            int n = blockStart + pp;
            if (n < N_) {
                float4 r = rg4[(size_t)n * 32 + d4];
                float4 e = eq4[(size_t)sidx[pp] * 32 + d4];
                float4 w;
                w.x = r.x - e.x; w.y = r.y - e.y; w.z = r.z - e.z; w.w = r.w - e.w;
                rg4[(size_t)n * 32 + d4] = w;
            }
        }
    } else {
        // ================ SIMT f32x2 half: points blockStart+128..+255 ====
        const int t2 = tid - 256;
        const int tx = t2 & 7;
        const int ty = t2 >> 3;          // 0..31
        const int base2 = blockStart + 128;

        float4* r4s  = (float4*)(smem + SM_SR);     // 128 x 33 float4
        float4* ebuf = (float4*)(smem + SM_SE);     // 2 x 1056 float4
        const float4* eq = (const float4*)(embed + (size_t)q * (K_ * D_));
        float4* rg = (float4*)g_resid;

        #pragma unroll
        for (int i = 0; i < 16; i++) {
            int f = t2 + 256 * i;
            int p = f >> 5, s0 = f & 31;
            int n = base2 + p;
            if (n >= N_) n = 0;
            r4s[p * 33 + s0] = rg[(size_t)n * 32 + s0];
        }

        float4 er[4];
        #pragma unroll
        for (int i = 0; i < 4; i++) {
            int f = t2 + 256 * i;
            er[i] = eq[(size_t)(f >> 5) * 32 + (f & 31)];
        }

        float best[4];
        int   bidx[4];
        #pragma unroll
        for (int j = 0; j < 4; j++) { best[j] = -3.4e38f; bidx[j] = 0; }

        for (int c = 0; c < 32; ++c) {
            float4* eb = ebuf + (c & 1) * 1056;
            #pragma unroll
            for (int i = 0; i < 4; i++) {
                int f = t2 + 256 * i;
                eb[(f >> 5) * 33 + (f & 31)] = er[i];
            }
            if (c < 31) {
                #pragma unroll
                for (int i = 0; i < 4; i++) {
                    int f = t2 + 256 * i;
                    er[i] = eq[(size_t)((c + 1) * 32 + (f >> 5)) * 32 + (f & 31)];
                }
            }
            float cn[4];
            #pragma unroll
            for (int jc = 0; jc < 4; jc++)
                cn[jc] = gcn[c * 32 + tx + 8 * jc];

            BAR_S();

            unsigned long long acc[4][4];
            #pragma unroll
            for (int a = 0; a < 4; a++)
                #pragma unroll
                for (int b2 = 0; b2 < 4; b2++) acc[a][b2] = 0ULL;

            #pragma unroll 2
            for (int d4 = 0; d4 < 32; ++d4) {
                float4 ra[4], ev[4];
                #pragma unroll
                for (int jp = 0; jp < 4; jp++)
                    ra[jp] = r4s[(ty + 32 * jp) * 33 + d4];
                #pragma unroll
                for (int jc = 0; jc < 4; jc++)
                    ev[jc] = eb[(tx + 8 * jc) * 33 + d4];
                #pragma unroll
                for (int jp = 0; jp < 4; jp++) {
                    const unsigned long long r01 = ((const unsigned long long*)&ra[jp])[0];
                    const unsigned long long r23 = ((const unsigned long long*)&ra[jp])[1];
                    #pragma unroll
                    for (int jc = 0; jc < 4; jc++) {
                        ffma2(acc[jp][jc], r01, ((const unsigned long long*)&ev[jc])[0]);
                        ffma2(acc[jp][jc], r23, ((const unsigned long long*)&ev[jc])[1]);
                    }
                }
            }

            #pragma unroll
            for (int jp = 0; jp < 4; jp++) {
                #pragma unroll
                for (int jc = 0; jc < 4; jc++) {
                    const unsigned long long a = acc[jp][jc];
                    const float lo = __uint_as_float((unsigned)(a & 0xffffffffu));
                    const float hi = __uint_as_float((unsigned)(a >> 32));
                    const float s  = 2.0f * (lo + hi) - cn[jc];
                    const int cg   = c * 32 + tx + 8 * jc;
                    if (s > best[jp]) { best[jp] = s; bidx[jp] = cg; }
                }
            }
        }

        #pragma unroll
        for (int jp = 0; jp < 4; jp++) {
            float v  = best[jp];
            int   ix = bidx[jp];
            #pragma unroll
            for (int delta = 1; delta < 8; delta <<= 1) {
                float ov = __shfl_xor_sync(0xffffffffu, v, delta);
                int   oi = __shfl_xor_sync(0xffffffffu, ix, delta);
                if (ov > v || (ov == v && oi < ix)) { v = ov; ix = oi; }
            }
            if (tx == 0) sidx[128 + ty + 32 * jp] = ix;
        }
        BAR_S();

        if (t2 < 128) {
            int n = base2 + t2;
            if (n < N_) out[(size_t)q * N_ + n] = (float)sidx[128 + t2];
        }
        #pragma unroll
        for (int i = 0; i < 16; i++) {
            int f = t2 + 256 * i;
            int p = f >> 5, d4 = f & 31;
            int n = base2 + p;
            if (n < N_) {
                float4 r = r4s[p * 33 + d4];
                float4 e = eq[(size_t)sidx[128 + p] * 32 + d4];
                float4 w;
                w.x = r.x - e.x; w.y = r.y - e.y; w.z = r.z - e.z; w.w = r.w - e.w;
                rg[(size_t)n * 32 + d4] = w;
            }
        }
    }
}

// ---------------------------------------------------------------------------
extern "C" void kernel_launch(void* const* d_in, const int* in_sizes, int n_in,
                              void* d_out, int out_size)
{
    const float* embeddings = (const float*)d_in[0];
    const float* embed      = (const float*)d_in[1];
    if (n_in >= 2 && in_sizes[0] == Q_ * K_ * D_ && in_sizes[1] == B_ * D_ * T_) {
        const float* t = embeddings; embeddings = embed; embed = t;
    }
    float* out = (float*)d_out;

    cudaFuncSetAttribute(rvq_hybrid_kernel,
                         cudaFuncAttributeMaxDynamicSharedMemorySize, SM_TOTAL);

    transpose_kernel<<<dim3(71, 4, 32), dim3(32, 8)>>>(embeddings);
    cnorm_kernel<<<4096, 256>>>(embed);
    prep_e2_kernel<<<Q_ * K_, 128>>>(embed);
    for (int q = 0; q < Q_; q++) {
        rvq_hybrid_kernel<<<NBLK, 512, SM_TOTAL>>>(embed, q, out);
    }
}